// round 10
// baseline (speedup 1.0000x reference)
#include <cuda_runtime.h>

#define D_    128
#define ED_   16
#define N_MAX 100000
#define L_MAX 5

// per-layer per-node projections, layout [layer][node][16]
__device__ __align__(128) float g_p[(size_t)L_MAX * N_MAX * ED_];
__device__ __align__(128) float g_q[(size_t)L_MAX * N_MAX * ED_];
// transposed projection weights: [layer][32 rows (16 p + 16 q)][128 k]
__device__ __align__(128) float g_wT[(size_t)L_MAX * 32 * 128];

// edge-MLP weights packed as float pairs for fma.rn.f32x2
__constant__ __align__(16) ulonglong2 cWC[L_MAX][64];
__constant__ __align__(16) ulonglong2 cW2[L_MAX][64];
__constant__ __align__(16) unsigned long long cB1[L_MAX][8];
__constant__ __align__(16) unsigned long long cB2[L_MAX][8];

// ---- f32x2 packed helpers ----
__device__ __forceinline__ unsigned long long pk2(float a) {
    unsigned long long r; asm("mov.b64 %0, {%1, %1};" : "=l"(r) : "f"(a)); return r;
}
__device__ __forceinline__ float2 up2(unsigned long long v) {
    float2 r; asm("mov.b64 {%0, %1}, %2;" : "=f"(r.x), "=f"(r.y) : "l"(v)); return r;
}
__device__ __forceinline__ unsigned long long fma2(unsigned long long a,
                                                   unsigned long long b,
                                                   unsigned long long c) {
    unsigned long long d;
    asm("fma.rn.f32x2 %0, %1, %2, %3;" : "=l"(d) : "l"(a), "l"(b), "l"(c));
    return d;
}
__device__ __forceinline__ unsigned long long add2(unsigned long long a,
                                                   unsigned long long b) {
    unsigned long long d;
    asm("add.rn.f32x2 %0, %1, %2;" : "=l"(d) : "l"(a), "l"(b));
    return d;
}

// transpose eW1's node-projection part into g_wT (once per launch, tiny)
__global__ void transpose_w_kernel(const float* __restrict__ eW1, int L)
{
    int idx = blockIdx.x * 256 + threadIdx.x;
    if (idx >= L * 4096) return;
    int l   = idx >> 12;
    int rem = idx & 4095;
    int r   = rem >> 7;          // 0..31 (0-15 = p cols, 16-31 = q cols)
    int k   = rem & 127;
    int j   = r & 15;
    int off = (r >= 16) ? 2048 : 0;    // Wb starts at row 128 (=2048 floats)
    g_wT[idx] = eW1[(size_t)l * 4352 + off + k * 16 + j];
}

// ---------------------------------------------------------------------------
// Edge MLP for one layer, one thread per edge (proven R9 shape).
// ---------------------------------------------------------------------------
__device__ __forceinline__ void edge_work(
    int bid, const int* __restrict__ src, const int* __restrict__ dst,
    const float* __restrict__ ea_in, float* __restrict__ ea_out,
    int layer, int e_total)
{
    int e = bid * 256 + threadIdx.x;
    if (e >= e_total) return;

    int si = src[e], di = dst[e];
    const ulonglong2* P =
        reinterpret_cast<const ulonglong2*>(g_p + ((size_t)layer * N_MAX + si) * 16);
    const ulonglong2* Q =
        reinterpret_cast<const ulonglong2*>(g_q + ((size_t)layer * N_MAX + di) * 16);

    unsigned long long h[8];
    #pragma unroll
    for (int i = 0; i < 4; ++i) {
        ulonglong2 pv = P[i], qv = Q[i];
        h[2*i+0] = add2(add2(pv.x, qv.x), cB1[layer][2*i+0]);
        h[2*i+1] = add2(add2(pv.y, qv.y), cB1[layer][2*i+1]);
    }

    const float4* EA = reinterpret_cast<const float4*>(ea_in + (size_t)e * 16);
    #pragma unroll
    for (int c = 0; c < 4; ++c) {
        float4 ev = EA[c];
        float es[4] = {ev.x, ev.y, ev.z, ev.w};
        #pragma unroll
        for (int kk = 0; kk < 4; ++kk) {
            int k = c * 4 + kk;
            unsigned long long ek = pk2(es[kk]);
            ulonglong2 w0 = cWC[layer][k*4+0], w1 = cWC[layer][k*4+1];
            ulonglong2 w2v = cWC[layer][k*4+2], w3 = cWC[layer][k*4+3];
            h[0] = fma2(ek, w0.x,  h[0]);  h[1] = fma2(ek, w0.y,  h[1]);
            h[2] = fma2(ek, w1.x,  h[2]);  h[3] = fma2(ek, w1.y,  h[3]);
            h[4] = fma2(ek, w2v.x, h[4]);  h[5] = fma2(ek, w2v.y, h[5]);
            h[6] = fma2(ek, w3.x,  h[6]);  h[7] = fma2(ek, w3.y,  h[7]);
        }
    }

    float z[16];
    #pragma unroll
    for (int i = 0; i < 8; ++i) {
        float2 hv = up2(h[i]);
        z[2*i]   = __fdividef(hv.x, 1.0f + __expf(-hv.x));   // silu
        z[2*i+1] = __fdividef(hv.y, 1.0f + __expf(-hv.y));
    }

    unsigned long long o[8];
    #pragma unroll
    for (int i = 0; i < 8; ++i) o[i] = cB2[layer][i];
    #pragma unroll
    for (int k = 0; k < 16; ++k) {
        unsigned long long zk = pk2(z[k]);
        ulonglong2 w0 = cW2[layer][k*4+0], w1 = cW2[layer][k*4+1];
        ulonglong2 w2v = cW2[layer][k*4+2], w3 = cW2[layer][k*4+3];
        o[0] = fma2(zk, w0.x,  o[0]);  o[1] = fma2(zk, w0.y,  o[1]);
        o[2] = fma2(zk, w1.x,  o[2]);  o[3] = fma2(zk, w1.y,  o[3]);
        o[4] = fma2(zk, w2v.x, o[4]);  o[5] = fma2(zk, w2v.y, o[5]);
        o[6] = fma2(zk, w3.x,  o[6]);  o[7] = fma2(zk, w3.y,  o[7]);
    }

    ulonglong2* OUT = reinterpret_cast<ulonglong2*>(ea_out + (size_t)e * 16);
    #pragma unroll
    for (int i = 0; i < 4; ++i)
        OUT[i] = make_ulonglong2(o[2*i], o[2*i+1]);
}

// ---------------------------------------------------------------------------
// LayerNorm + projections for ONE layer. 8 warps x 4 rows per block.
// rowbuf in static smem (16KB); proj weights via L1-cached LDG of g_wT.
// ---------------------------------------------------------------------------
__device__ __forceinline__ void ln_work(
    int lnbid, float* rowbuf,
    const float* __restrict__ s_in, float* __restrict__ s_out,
    const float* __restrict__ lnw, const float* __restrict__ lnb,
    int layer, int n)
{
    int warp = threadIdx.x >> 5, lane = threadIdx.x & 31;
    float* rb = rowbuf + warp * 512;
    int j = lane & 15;
    int rowsel = (lane < 16) ? 0 : 16;
    float* dstbase = (lane < 16) ? g_p : g_q;

    int row0 = lnbid * 32 + warp * 4;
    if (row0 >= n) return;
    int nr = n - row0; if (nr > 4) nr = 4;

    float4 wv = reinterpret_cast<const float4*>(lnw + layer * 128)[lane];
    float4 bv = reinterpret_cast<const float4*>(lnb + layer * 128)[lane];

    float4 v[4];
    #pragma unroll
    for (int r = 0; r < 4; ++r) {
        int rr = (r < nr) ? r : 0;
        v[r] = reinterpret_cast<const float4*>(s_in)[(size_t)(row0 + rr) * 32 + lane];
    }

    float s1[4], s2[4];
    #pragma unroll
    for (int r = 0; r < 4; ++r) {
        s1[r] = (v[r].x + v[r].y) + (v[r].z + v[r].w);
        s2[r] = fmaf(v[r].x, v[r].x,
                fmaf(v[r].y, v[r].y,
                fmaf(v[r].z, v[r].z, v[r].w * v[r].w)));
    }
    #pragma unroll
    for (int o = 16; o; o >>= 1) {
        #pragma unroll
        for (int r = 0; r < 4; ++r) {
            s1[r] += __shfl_xor_sync(0xffffffffu, s1[r], o);
            s2[r] += __shfl_xor_sync(0xffffffffu, s2[r], o);
        }
    }
    #pragma unroll
    for (int r = 0; r < 4; ++r) {
        float mu = s1[r] * 0.0078125f;
        float rstd = rsqrtf(fmaf(s2[r], 0.0078125f, -mu * mu) + 1e-5f);
        v[r].x = (v[r].x - mu) * rstd * wv.x + bv.x;
        v[r].y = (v[r].y - mu) * rstd * wv.y + bv.y;
        v[r].z = (v[r].z - mu) * rstd * wv.z + bv.z;
        v[r].w = (v[r].w - mu) * rstd * wv.w + bv.w;
        reinterpret_cast<float4*>(rb + r * 128)[lane] = v[r];
        if (r < nr)
            reinterpret_cast<float4*>(s_out)[(size_t)(row0 + r) * 32 + lane] = v[r];
    }
    __syncwarp();

    const ulonglong2* wrow = reinterpret_cast<const ulonglong2*>(
        g_wT + ((size_t)layer * 32 + rowsel + j) * 128);
    unsigned long long acc[4] = {0, 0, 0, 0};
    #pragma unroll
    for (int c = 0; c < 32; ++c) {
        ulonglong2 w = __ldg(wrow + c);
        #pragma unroll
        for (int r = 0; r < 4; ++r) {
            ulonglong2 rv = reinterpret_cast<const ulonglong2*>(rb + r * 128)[c];
            acc[r] = fma2(rv.x, w.x, acc[r]);
            acc[r] = fma2(rv.y, w.y, acc[r]);
        }
    }
    #pragma unroll
    for (int r = 0; r < 4; ++r) {
        if (r < nr) {
            float2 a = up2(acc[r]);
            dstbase[((size_t)layer * N_MAX + (row0 + r)) * 16 + j] = a.x + a.y;
        }
    }
}

// ---------------------------------------------------------------------------
// Combined stage kernel: blocks [0,EB) do edge(edge_layer), blocks [EB, ...)
// do LN(ln_layer). Mixed CTAs co-reside per SM so LN's FMA/LDS issue fills
// the slots edge warps leave idle while waiting on random gathers.
// ---------------------------------------------------------------------------
__global__ __launch_bounds__(256) void stage_kernel(
    const int* __restrict__ src, const int* __restrict__ dst,
    const float* __restrict__ ea_in, float* __restrict__ ea_out,
    int edge_layer, int e_total, int EB,
    const float* __restrict__ s_in, float* __restrict__ s_out,
    const float* __restrict__ lnw, const float* __restrict__ lnb,
    int ln_layer, int n)
{
    __shared__ __align__(16) float rowbuf[8 * 512];   // 16KB, LN path only
    int bid = blockIdx.x;
    if (bid < EB) {
        edge_work(bid, src, dst, ea_in, ea_out, edge_layer, e_total);
    } else {
        ln_work(bid - EB, rowbuf, s_in, s_out, lnw, lnb, ln_layer, n);
    }
}

extern "C" void kernel_launch(void* const* d_in, const int* in_sizes, int n_in,
                              void* d_out, int out_size)
{
    const float* s0   = (const float*)d_in[0];       // [N,128]
    const int*   ei   = (const int*)d_in[1];         // [2,E] int32
    const float* ea0  = (const float*)d_in[2];       // [E,16]
    const float* lnw  = (const float*)d_in[4];       // [L,128]
    const float* lnb  = (const float*)d_in[5];       // [L,128]
    const float* eW1  = (const float*)d_in[6];       // [L,272,16]
    const float* eb1  = (const float*)d_in[7];       // [L,16]
    const float* eW2  = (const float*)d_in[8];       // [L,16,16]
    const float* eb2  = (const float*)d_in[9];       // [L,16]
    // batch / nW1 / nb1 / nW2 / nb2 are dead in the reference dataflow

    int n = in_sizes[0] / D_;
    int e = in_sizes[2] / ED_;
    int L = in_sizes[4] / D_;

    float* out    = (float*)d_out;
    float* s_buf  = out;                      // final s
    float* ea_buf = out + (size_t)n * D_;     // final edge_attr

    const int* src = ei;
    const int* dst = ei + e;

    // prep: transpose projection weights; stage edge-MLP weights to constants
    transpose_w_kernel<<<(L * 4096 + 255) / 256, 256>>>(eW1, L);

    void *pWC, *pW2, *pB1, *pB2;
    cudaGetSymbolAddress(&pWC, cWC);
    cudaGetSymbolAddress(&pW2, cW2);
    cudaGetSymbolAddress(&pB1, cB1);
    cudaGetSymbolAddress(&pB2, cB2);
    cudaMemcpy2DAsync(pWC, 1024, eW1 + 256 * 16, 272 * 16 * 4, 1024, L,
                      cudaMemcpyDeviceToDevice);
    cudaMemcpyAsync(pW2, eW2, (size_t)L * 256 * 4, cudaMemcpyDeviceToDevice);
    cudaMemcpyAsync(pB1, eb1, (size_t)L * 16 * 4, cudaMemcpyDeviceToDevice);
    cudaMemcpyAsync(pB2, eb2, (size_t)L * 16 * 4, cudaMemcpyDeviceToDevice);

    int EB  = (e + 255) / 256;       // edge blocks
    int LNB = (n + 31) / 32;         // ln blocks (8 warps x 4 rows)

    // K0: LN layer 0 alone (reads s0, writes s_buf)
    stage_kernel<<<LNB, 256>>>(src, dst, ea0, ea_buf, 0, 0, 0,
                               s0, s_buf, lnw, lnb, 0, n);

    // K1..K(L-1): edge(l) || LN(l+1);  KL: edge(L-1) alone
    for (int l = 0; l < L; ++l) {
        int lnl = l + 1;
        int lnb_count = (lnl < L) ? LNB : 0;
        stage_kernel<<<EB + lnb_count, 256>>>(
            src, dst,
            (l == 0) ? ea0 : ea_buf, ea_buf,
            l, e, EB,
            s_buf, s_buf, lnw, lnb, lnl, n);
    }
}

// round 11
// speedup vs baseline: 2.2831x; 2.2831x over previous
#include <cuda_runtime.h>

#define D_    128
#define ED_   16
#define N_MAX 100000
#define L_MAX 5

// per-layer per-node projections, layout [layer][node][16]
__device__ __align__(128) float g_p[(size_t)L_MAX * N_MAX * ED_];
__device__ __align__(128) float g_q[(size_t)L_MAX * N_MAX * ED_];

// edge-MLP weights packed as float pairs for fma.rn.f32x2
__constant__ __align__(16) ulonglong2 cWC[L_MAX][64];
__constant__ __align__(16) ulonglong2 cW2[L_MAX][64];
__constant__ __align__(16) unsigned long long cB1[L_MAX][8];
__constant__ __align__(16) unsigned long long cB2[L_MAX][8];

// ---- f32x2 packed helpers ----
__device__ __forceinline__ unsigned long long pk2(float a) {
    unsigned long long r; asm("mov.b64 %0, {%1, %1};" : "=l"(r) : "f"(a)); return r;
}
__device__ __forceinline__ float2 up2(unsigned long long v) {
    float2 r; asm("mov.b64 {%0, %1}, %2;" : "=f"(r.x), "=f"(r.y) : "l"(v)); return r;
}
__device__ __forceinline__ unsigned long long fma2(unsigned long long a,
                                                   unsigned long long b,
                                                   unsigned long long c) {
    unsigned long long d;
    asm("fma.rn.f32x2 %0, %1, %2, %3;" : "=l"(d) : "l"(a), "l"(b), "l"(c));
    return d;
}
__device__ __forceinline__ unsigned long long add2(unsigned long long a,
                                                   unsigned long long b) {
    unsigned long long d;
    asm("add.rn.f32x2 %0, %1, %2;" : "=l"(d) : "l"(a), "l"(b));
    return d;
}

// ---------------------------------------------------------------------------
// All L layers of LayerNorm + both 128->16 projections. 8 rows per warp,
// rows live in registers across layers. SPLIT-K projection: lanes 0-15 cover
// k in [0,64), lanes 16-31 cover k in [64,128); each lane accumulates BOTH
// its p-column and q-column; shfl_xor(16) combines the halves. This halves
// rowbuf crossbar traffic (the measured LN bottleneck).
// Rowbuf rows are 132 floats: [k0..63][pad 4][k64..127] so the two broadcast
// addresses per LDS hit disjoint banks.
// ---------------------------------------------------------------------------
#define LNW 16   // warps per block
__global__ __launch_bounds__(512) void ln_all_kernel(
    const float* __restrict__ s_in, float* __restrict__ s_out,
    const float* __restrict__ lnw, const float* __restrict__ lnb,
    const float* __restrict__ eW1 /* [L,272,16] */, int n, int L)
{
    extern __shared__ __align__(16) float sm[];
    float* wT     = sm;                       // [5][32*132] transposed Wa|Wb
    float* sLn    = wT + L_MAX * 4224;        // [5][256] lnw|lnb
    float* rowbuf = sLn + L_MAX * 256;        // [LNW warps][8*132]

    for (int l = 0; l < L; ++l) {
        const float* w1 = eW1 + (size_t)l * 272 * 16;
        float* wTl = wT + l * 4224;
        for (int idx = threadIdx.x; idx < 2048; idx += 512) {
            int k = idx >> 4, j = idx & 15;
            wTl[j * 132 + k]        = w1[idx];          // Wa
            wTl[(16 + j) * 132 + k] = w1[2048 + idx];   // Wb
        }
        for (int idx = threadIdx.x; idx < 128; idx += 512) {
            sLn[l * 256 + idx]       = lnw[l * 128 + idx];
            sLn[l * 256 + 128 + idx] = lnb[l * 128 + idx];
        }
    }
    __syncthreads();

    int warp = threadIdx.x >> 5, lane = threadIdx.x & 31;
    float* rb = rowbuf + warp * (8 * 132);
    int j = lane & 15;
    int h = lane >> 4;                         // k-half
    // STS offset: cols 4*lane, with +4 pad for upper half
    int sts_off = 4 * lane + (h ? 4 : 0);
    // LDS offset for own k-half
    int lds_off = h ? 68 : 0;
    float* dstbase = (h == 0) ? g_p : g_q;

    int stride = gridDim.x * LNW * 8;
    for (int row0 = (blockIdx.x * LNW + warp) * 8; row0 < n; row0 += stride) {
        int nr = n - row0; if (nr > 8) nr = 8;

        float4 v[8];
        #pragma unroll
        for (int r = 0; r < 8; ++r) {
            int rr = (r < nr) ? r : (nr - 1);
            v[r] = reinterpret_cast<const float4*>(s_in)[(size_t)(row0 + rr) * 32 + lane];
        }

        for (int l = 0; l < L; ++l) {
            const float4* lnp = reinterpret_cast<const float4*>(sLn + l * 256);
            float4 wv = lnp[lane], bv = lnp[32 + lane];

            float s1[8], s2[8];
            #pragma unroll
            for (int r = 0; r < 8; ++r) {
                s1[r] = (v[r].x + v[r].y) + (v[r].z + v[r].w);
                s2[r] = fmaf(v[r].x, v[r].x,
                        fmaf(v[r].y, v[r].y,
                        fmaf(v[r].z, v[r].z, v[r].w * v[r].w)));
            }
            #pragma unroll
            for (int o = 16; o; o >>= 1) {
                #pragma unroll
                for (int r = 0; r < 8; ++r) {
                    s1[r] += __shfl_xor_sync(0xffffffffu, s1[r], o);
                    s2[r] += __shfl_xor_sync(0xffffffffu, s2[r], o);
                }
            }
            #pragma unroll
            for (int r = 0; r < 8; ++r) {
                float mu = s1[r] * 0.0078125f;
                float rstd = rsqrtf(fmaf(s2[r], 0.0078125f, -mu * mu) + 1e-5f);
                v[r].x = (v[r].x - mu) * rstd * wv.x + bv.x;
                v[r].y = (v[r].y - mu) * rstd * wv.y + bv.y;
                v[r].z = (v[r].z - mu) * rstd * wv.z + bv.z;
                v[r].w = (v[r].w - mu) * rstd * wv.w + bv.w;
                *reinterpret_cast<float4*>(rb + r * 132 + sts_off) = v[r];
            }
            __syncwarp();

            // split-k projection: this lane covers its k-half for BOTH
            // p column j and q column j
            const float* wbase = wT + l * 4224;
            const ulonglong2* wp =
                reinterpret_cast<const ulonglong2*>(wbase + j * 132 + h * 64);
            const ulonglong2* wq =
                reinterpret_cast<const ulonglong2*>(wbase + (16 + j) * 132 + h * 64);

            unsigned long long ap[8] = {0,0,0,0,0,0,0,0};
            unsigned long long aq[8] = {0,0,0,0,0,0,0,0};
            #pragma unroll
            for (int c = 0; c < 16; ++c) {
                ulonglong2 wpv = wp[c];
                ulonglong2 wqv = wq[c];
                #pragma unroll
                for (int r = 0; r < 8; ++r) {
                    ulonglong2 rv = *reinterpret_cast<const ulonglong2*>(
                        rb + r * 132 + lds_off + c * 4);
                    ap[r] = fma2(rv.x, wpv.x, ap[r]);
                    ap[r] = fma2(rv.y, wpv.y, ap[r]);
                    aq[r] = fma2(rv.x, wqv.x, aq[r]);
                    aq[r] = fma2(rv.y, wqv.y, aq[r]);
                }
            }
            #pragma unroll
            for (int r = 0; r < 8; ++r) {
                unsigned long long op = __shfl_xor_sync(0xffffffffu, ap[r], 16);
                unsigned long long oq = __shfl_xor_sync(0xffffffffu, aq[r], 16);
                unsigned long long tot = (h == 0) ? add2(ap[r], op) : add2(aq[r], oq);
                float2 a = up2(tot);
                if (r < nr)
                    dstbase[((size_t)l * N_MAX + (row0 + r)) * 16 + j] = a.x + a.y;
            }
            __syncwarp();
        }

        #pragma unroll
        for (int r = 0; r < 8; ++r)
            if (r < nr)
                reinterpret_cast<float4*>(s_out)[(size_t)(row0 + r) * 32 + lane] = v[r];
    }
}

// ---------------------------------------------------------------------------
// One thread per edge, one layer per launch (R9 proven-best shape):
// direct LDG.128 gathers, constant-port weights, 8 f32x2 accumulators.
// ---------------------------------------------------------------------------
__global__ __launch_bounds__(256) void edge_kernel(
    const int* __restrict__ src, const int* __restrict__ dst,
    const float* __restrict__ ea_in, float* __restrict__ ea_out,
    int layer, int e_total)
{
    int e = blockIdx.x * 256 + threadIdx.x;
    if (e >= e_total) return;

    int si = src[e], di = dst[e];
    const ulonglong2* P =
        reinterpret_cast<const ulonglong2*>(g_p + ((size_t)layer * N_MAX + si) * 16);
    const ulonglong2* Q =
        reinterpret_cast<const ulonglong2*>(g_q + ((size_t)layer * N_MAX + di) * 16);

    unsigned long long h[8];
    #pragma unroll
    for (int i = 0; i < 4; ++i) {
        ulonglong2 pv = P[i], qv = Q[i];
        h[2*i+0] = add2(add2(pv.x, qv.x), cB1[layer][2*i+0]);
        h[2*i+1] = add2(add2(pv.y, qv.y), cB1[layer][2*i+1]);
    }

    const float4* EA = reinterpret_cast<const float4*>(ea_in + (size_t)e * 16);
    #pragma unroll
    for (int c = 0; c < 4; ++c) {
        float4 ev = EA[c];
        float es[4] = {ev.x, ev.y, ev.z, ev.w};
        #pragma unroll
        for (int kk = 0; kk < 4; ++kk) {
            int k = c * 4 + kk;
            unsigned long long ek = pk2(es[kk]);
            ulonglong2 w0 = cWC[layer][k*4+0], w1 = cWC[layer][k*4+1];
            ulonglong2 w2v = cWC[layer][k*4+2], w3 = cWC[layer][k*4+3];
            h[0] = fma2(ek, w0.x,  h[0]);  h[1] = fma2(ek, w0.y,  h[1]);
            h[2] = fma2(ek, w1.x,  h[2]);  h[3] = fma2(ek, w1.y,  h[3]);
            h[4] = fma2(ek, w2v.x, h[4]);  h[5] = fma2(ek, w2v.y, h[5]);
            h[6] = fma2(ek, w3.x,  h[6]);  h[7] = fma2(ek, w3.y,  h[7]);
        }
    }

    float z[16];
    #pragma unroll
    for (int i = 0; i < 8; ++i) {
        float2 hv = up2(h[i]);
        z[2*i]   = __fdividef(hv.x, 1.0f + __expf(-hv.x));   // silu
        z[2*i+1] = __fdividef(hv.y, 1.0f + __expf(-hv.y));
    }

    unsigned long long o[8];
    #pragma unroll
    for (int i = 0; i < 8; ++i) o[i] = cB2[layer][i];
    #pragma unroll
    for (int k = 0; k < 16; ++k) {
        unsigned long long zk = pk2(z[k]);
        ulonglong2 w0 = cW2[layer][k*4+0], w1 = cW2[layer][k*4+1];
        ulonglong2 w2v = cW2[layer][k*4+2], w3 = cW2[layer][k*4+3];
        o[0] = fma2(zk, w0.x,  o[0]);  o[1] = fma2(zk, w0.y,  o[1]);
        o[2] = fma2(zk, w1.x,  o[2]);  o[3] = fma2(zk, w1.y,  o[3]);
        o[4] = fma2(zk, w2v.x, o[4]);  o[5] = fma2(zk, w2v.y, o[5]);
        o[6] = fma2(zk, w3.x,  o[6]);  o[7] = fma2(zk, w3.y,  o[7]);
    }

    ulonglong2* OUT = reinterpret_cast<ulonglong2*>(ea_out + (size_t)e * 16);
    #pragma unroll
    for (int i = 0; i < 4; ++i)
        OUT[i] = make_ulonglong2(o[2*i], o[2*i+1]);
}

extern "C" void kernel_launch(void* const* d_in, const int* in_sizes, int n_in,
                              void* d_out, int out_size)
{
    const float* s0   = (const float*)d_in[0];       // [N,128]
    const int*   ei   = (const int*)d_in[1];         // [2,E] int32
    const float* ea0  = (const float*)d_in[2];       // [E,16]
    const float* lnw  = (const float*)d_in[4];       // [L,128]
    const float* lnb  = (const float*)d_in[5];       // [L,128]
    const float* eW1  = (const float*)d_in[6];       // [L,272,16]
    const float* eb1  = (const float*)d_in[7];       // [L,16]
    const float* eW2  = (const float*)d_in[8];       // [L,16,16]
    const float* eb2  = (const float*)d_in[9];       // [L,16]
    // batch / nW1 / nb1 / nW2 / nb2 are dead in the reference dataflow

    int n = in_sizes[0] / D_;
    int e = in_sizes[2] / ED_;
    int L = in_sizes[4] / D_;

    float* out    = (float*)d_out;
    float* s_buf  = out;                      // final s
    float* ea_buf = out + (size_t)n * D_;     // final edge_attr

    const int* src = ei;
    const int* dst = ei + e;

    // stage edge-MLP weights into constant memory (capturable D2D copies)
    void *pWC, *pW2, *pB1, *pB2;
    cudaGetSymbolAddress(&pWC, cWC);
    cudaGetSymbolAddress(&pW2, cW2);
    cudaGetSymbolAddress(&pB1, cB1);
    cudaGetSymbolAddress(&pB2, cB2);
    cudaMemcpy2DAsync(pWC, 1024, eW1 + 256 * 16, 272 * 16 * 4, 1024, L,
                      cudaMemcpyDeviceToDevice);
    cudaMemcpyAsync(pW2, eW2, (size_t)L * 256 * 4, cudaMemcpyDeviceToDevice);
    cudaMemcpyAsync(pB1, eb1, (size_t)L * 16 * 4, cudaMemcpyDeviceToDevice);
    cudaMemcpyAsync(pB2, eb2, (size_t)L * 16 * 4, cudaMemcpyDeviceToDevice);

    size_t shmem = (size_t)(L_MAX * 4224 + L_MAX * 256 + LNW * 8 * 132) * 4;
    cudaFuncSetAttribute(ln_all_kernel,
                         cudaFuncAttributeMaxDynamicSharedMemorySize, (int)shmem);

    ln_all_kernel<<<148, 512, shmem>>>(s0, s_buf, lnw, lnb, eW1, n, L);

    int edge_blocks = (e + 255) / 256;
    for (int i = 0; i < L; ++i)
        edge_kernel<<<edge_blocks, 256>>>(
            src, dst,
            (i == 0) ? ea0 : ea_buf, ea_buf,
            i, e);
}